// round 1
// baseline (speedup 1.0000x reference)
#include <cuda_runtime.h>

#define N_NODES 50000
#define N_EDGES 600000
#define N_MOL   512
#define NF      30     // atom features
#define AC      104    // a channels (64 + 24 + 16)
#define FC      216    // e_feat channels (64 + 72 + 80)

// ---------------- scratch (device globals; no allocation) ----------------
__device__ float g_A[(size_t)N_NODES * AC];     // x @ W1 / sqrt(30), per node (20.8 MB)
__device__ float g_n[(size_t)N_NODES * FC];     // segment-summed edge features (43.2 MB)
__device__ float g_deg[N_NODES];
__device__ float g_isd[N_NODES];                // inv sqrt degree
__device__ float g_nodesum[N_NODES];            // per-node out_e sum
__device__ float g_acc[N_MOL];
__device__ float g_atoms[N_MOL];

// ---------------- constants ----------------
__device__ __forceinline__ void compute_ea(float x, float y, float z, float w, float* ea) {
    const float s3  = 1.7320508075688772f;   // sqrt(3)
    const float s5  = 2.2360679774997896f;   // sqrt(5)
    const float s15 = 3.8729833462074170f;   // sqrt(15)
    float r2 = x * x + y * y + z * z;
    ea[0] = w;
    ea[1] = w * s3 * x;
    ea[2] = w * s3 * y;
    ea[3] = w * s3 * z;
    ea[4] = w * s15 * x * y;
    ea[5] = w * s15 * y * z;
    ea[6] = w * 0.5f * s5 * (3.0f * z * z - r2);
    ea[7] = w * s15 * x * z;
    ea[8] = w * 0.5f * s15 * (x * x - y * y);
}

// ---------------- kernel 0: zero scratch ----------------
__global__ void k_zero() {
    size_t i = (size_t)blockIdx.x * blockDim.x + threadIdx.x;
    if (i < (size_t)N_NODES * FC) g_n[i] = 0.0f;
    if (i < N_NODES) { g_deg[i] = 0.0f; g_nodesum[i] = 0.0f; }
    if (i < N_MOL)   { g_acc[i] = 0.0f; g_atoms[i] = 0.0f; }
}

// ---------------- kernel 1: A = x @ W1 * 1/sqrt(30), one block per node ----------------
__global__ void k_nodeA(const float* __restrict__ x,
                        const float* __restrict__ W1_0,
                        const float* __restrict__ W1_1,
                        const float* __restrict__ W1_2) {
    __shared__ float sx[NF];
    int nid = blockIdx.x;
    int t = threadIdx.x;
    if (t < NF) sx[t] = x[(size_t)nid * NF + t];
    __syncthreads();
    if (t < AC) {
        const float* wp;
        int stride;
        if (t < 64)      { wp = W1_0 + t;      stride = 64; }
        else if (t < 88) { wp = W1_1 + (t-64); stride = 24; }
        else             { wp = W1_2 + (t-88); stride = 16; }
        float acc = 0.0f;
        #pragma unroll
        for (int k = 0; k < NF; k++)
            acc = fmaf(sx[k], wp[(size_t)k * stride], acc);
        g_A[(size_t)nid * AC + t] = acc * 0.18257418583505536f; // 1/sqrt(30)
    }
}

// ---------------- kernel 2: per-edge scatter of e_feat into g_n (warp per edge) ----------------
__global__ void k_edge_scatter(const float* __restrict__ pos,
                               const float* __restrict__ eattr,
                               const int*   __restrict__ esrc,
                               const int*   __restrict__ edst) {
    int gtid = blockIdx.x * blockDim.x + threadIdx.x;
    int e    = gtid >> 5;
    int lane = threadIdx.x & 31;
    int wslot = threadIdx.x >> 5;
    __shared__ float sA[8][AC];   // 256 threads -> 8 warps per block
    if (e >= N_EDGES) return;

    int src = esrc[e];
    int dst = edst[e];

    // stage a-row (L2-resident table)
    #pragma unroll
    for (int i = lane; i < AC; i += 32)
        sA[wslot][i] = g_A[(size_t)src * AC + i];

    // spherical harmonics * edge_attr[:,0] (broadcast loads, redundant per lane)
    float vx = pos[src * 3 + 0] - pos[dst * 3 + 0];
    float vy = pos[src * 3 + 1] - pos[dst * 3 + 1];
    float vz = pos[src * 3 + 2] - pos[dst * 3 + 2];
    float w  = eattr[(size_t)e * 10];
    float ea[9];
    compute_ea(vx, vy, vz, w, ea);
    __syncwarp();

    float* np = g_n + (size_t)dst * FC;
    #pragma unroll
    for (int c = lane; c < FC; c += 32) {
        float v;
        if (c < 64) {
            v = sA[wslot][c] * ea[0];
        } else if (c < 136) {
            int t = c - 64; int u = t / 3; int m = t - 3 * u;
            v = sA[wslot][64 + u] * ea[1 + m];
        } else {
            int t = c - 136; int u = t / 5; int m = t - 5 * u;
            v = sA[wslot][88 + u] * ea[4 + m];
        }
        atomicAdd(np + c, v);
    }
    if (lane == 0) atomicAdd(&g_deg[dst], 1.0f);
}

// ---------------- kernel 3: inv sqrt degree ----------------
__global__ void k_isd() {
    int i = blockIdx.x * blockDim.x + threadIdx.x;
    if (i < N_NODES) {
        float d = g_deg[i];
        g_isd[i] = (d > 0.0f) ? rsqrtf(fmaxf(d, 1.0f)) : 0.0f;
    }
}

// ---------------- kernel 4: per-edge gather + contraction -> nodesum (warp per edge) ----------------
__global__ void k_edge_gather(const float* __restrict__ pos,
                              const float* __restrict__ eattr,
                              const int*   __restrict__ esrc,
                              const int*   __restrict__ edst,
                              const float* __restrict__ W2_0,
                              const float* __restrict__ W2_1,
                              const float* __restrict__ W2_2) {
    int gtid = blockIdx.x * blockDim.x + threadIdx.x;
    int e    = gtid >> 5;
    int lane = threadIdx.x & 31;
    if (e >= N_EDGES) return;

    int src = esrc[e];
    int dst = edst[e];

    float vx = pos[src * 3 + 0] - pos[dst * 3 + 0];
    float vy = pos[src * 3 + 1] - pos[dst * 3 + 1];
    float vz = pos[src * 3 + 2] - pos[dst * 3 + 2];
    float w  = eattr[(size_t)e * 10];
    float ea[9];
    compute_ea(vx, vy, vz, w, ea);

    const float inv_s3 = 0.5773502691896258f;  // 1/sqrt(3)
    const float inv_s5 = 0.4472135954999579f;  // 1/sqrt(5)

    const float* np = g_n + (size_t)src * FC;
    float partial = 0.0f;
    #pragma unroll
    for (int c = lane; c < FC; c += 32) {
        float coef;
        if (c < 64) {
            coef = ea[0] * W2_0[c];
        } else if (c < 136) {
            int t = c - 64; int u = t / 3; int m = t - 3 * u;
            coef = ea[1 + m] * W2_1[u] * inv_s3;
        } else {
            int t = c - 136; int u = t / 5; int m = t - 5 * u;
            coef = ea[4 + m] * W2_2[u] * inv_s5;
        }
        partial = fmaf(np[c], coef, partial);
    }
    #pragma unroll
    for (int o = 16; o > 0; o >>= 1)
        partial += __shfl_xor_sync(0xFFFFFFFFu, partial, o);

    if (lane == 0) {
        // g = n[src] * isd[src]; out_e scaled by 1/sqrt(104)
        float out_e = partial * g_isd[src] * 0.09805806756909202f;
        atomicAdd(&g_nodesum[dst], out_e);
    }
}

// ---------------- kernel 5: node -> molecule ----------------
__global__ void k_node_to_mol(const int* __restrict__ batch) {
    int i = blockIdx.x * blockDim.x + threadIdx.x;
    if (i < N_NODES) {
        float v = g_nodesum[i] * g_isd[i];
        int m = batch[i];
        atomicAdd(&g_acc[m], v);
        atomicAdd(&g_atoms[m], 1.0f);
    }
}

// ---------------- kernel 6: finalize ----------------
__global__ void k_finalize(float* __restrict__ out) {
    int m = blockIdx.x * blockDim.x + threadIdx.x;
    if (m < N_MOL) {
        float a = g_atoms[m];
        out[m] = g_acc[m] * ((a > 0.0f) ? rsqrtf(fmaxf(a, 1.0f)) : 0.0f);
    }
}

// ---------------- launch ----------------
extern "C" void kernel_launch(void* const* d_in, const int* in_sizes, int n_in,
                              void* d_out, int out_size) {
    (void)in_sizes; (void)n_in; (void)out_size;
    const float* pos   = (const float*)d_in[0];
    const float* x     = (const float*)d_in[1];
    const float* eattr = (const float*)d_in[2];
    const float* W1_0  = (const float*)d_in[3];
    const float* W1_1  = (const float*)d_in[4];
    const float* W1_2  = (const float*)d_in[5];
    const float* W2_0  = (const float*)d_in[6];
    const float* W2_1  = (const float*)d_in[7];
    const float* W2_2  = (const float*)d_in[8];
    const int* esrc    = (const int*)d_in[9];
    const int* edst    = (const int*)d_in[10];
    const int* batch   = (const int*)d_in[11];
    float* out = (float*)d_out;

    // zero scratch (covers N_NODES*FC, the largest array)
    {
        size_t total = (size_t)N_NODES * FC;
        int blocks = (int)((total + 255) / 256);
        k_zero<<<blocks, 256>>>();
    }

    k_nodeA<<<N_NODES, 128>>>(x, W1_0, W1_1, W1_2);

    {
        long long threads = (long long)N_EDGES * 32;
        int blocks = (int)((threads + 255) / 256);
        k_edge_scatter<<<blocks, 256>>>(pos, eattr, esrc, edst);
    }

    k_isd<<<(N_NODES + 255) / 256, 256>>>();

    {
        long long threads = (long long)N_EDGES * 32;
        int blocks = (int)((threads + 255) / 256);
        k_edge_gather<<<blocks, 256>>>(pos, eattr, esrc, edst, W2_0, W2_1, W2_2);
    }

    k_node_to_mol<<<(N_NODES + 255) / 256, 256>>>(batch);
    k_finalize<<<(N_MOL + 255) / 256, 256>>>(out);
}

// round 2
// speedup vs baseline: 4.9476x; 4.9476x over previous
#include <cuda_runtime.h>

#define N_NODES 50000
#define N_EDGES 600000
#define N_MOL   512
#define NF      30

// ---------------- scratch (device globals; no allocation) ----------------
__device__ float g_V[3 * NF];                 // V_l[k] = sum_u W1_l[k,u]*W2_l[u] / sqrt(30)
__device__ float g_b[(size_t)N_NODES * 3];    // b = x @ V           (600 KB)
__device__ float g_h[(size_t)N_NODES * 9];    // scattered, then *isd (1.8 MB)
__device__ float g_w[N_EDGES];                // edge_attr[:,0] compacted (2.4 MB)
__device__ float g_deg[N_NODES];
__device__ float g_isd[N_NODES];
__device__ float g_nodesum[N_NODES];
__device__ float g_acc[N_MOL];
__device__ float g_atoms[N_MOL];

__device__ __forceinline__ void compute_ea(float x, float y, float z, float w, float* ea) {
    const float s3  = 1.7320508075688772f;
    const float s5  = 2.2360679774997896f;
    const float s15 = 3.8729833462074170f;
    float r2 = x * x + y * y + z * z;
    ea[0] = w;
    ea[1] = w * s3 * x;
    ea[2] = w * s3 * y;
    ea[3] = w * s3 * z;
    ea[4] = w * s15 * x * y;
    ea[5] = w * s15 * y * z;
    ea[6] = w * 0.5f * s5 * (3.0f * z * z - r2);
    ea[7] = w * s15 * x * z;
    ea[8] = w * 0.5f * s15 * (x * x - y * y);
}

// ---------------- kernel 0: zero scratch ----------------
__global__ void k_zero() {
    int i = blockIdx.x * blockDim.x + threadIdx.x;
    if (i < N_NODES * 9) g_h[i] = 0.0f;
    if (i < N_NODES) { g_deg[i] = 0.0f; g_nodesum[i] = 0.0f; }
    if (i < N_MOL)   { g_acc[i] = 0.0f; g_atoms[i] = 0.0f; }
}

// ---------------- kernel 1: V = (W1_l @ W2_l)/sqrt(30)  (one small block) ----------------
__global__ void k_V(const float* __restrict__ W1_0,
                    const float* __restrict__ W1_1,
                    const float* __restrict__ W1_2,
                    const float* __restrict__ W2_0,
                    const float* __restrict__ W2_1,
                    const float* __restrict__ W2_2) {
    int t = threadIdx.x;
    const float inv_s30 = 0.18257418583505536f;
    if (t < NF) {
        float acc = 0.0f;
        #pragma unroll
        for (int u = 0; u < 64; u++) acc = fmaf(W1_0[t * 64 + u], W2_0[u], acc);
        g_V[t] = acc * inv_s30;
    } else if (t < 2 * NF) {
        int k = t - NF;
        float acc = 0.0f;
        #pragma unroll
        for (int u = 0; u < 24; u++) acc = fmaf(W1_1[k * 24 + u], W2_1[u], acc);
        g_V[t] = acc * inv_s30;
    } else if (t < 3 * NF) {
        int k = t - 2 * NF;
        float acc = 0.0f;
        #pragma unroll
        for (int u = 0; u < 16; u++) acc = fmaf(W1_2[k * 16 + u], W2_2[u], acc);
        g_V[t] = acc * inv_s30;
    }
}

// ---------------- kernel 2: b = x @ V  (thread per node) ----------------
__global__ void k_b(const float* __restrict__ x) {
    __shared__ float sV[3 * NF];
    int t = threadIdx.x;
    if (t < 3 * NF) sV[t] = g_V[t];
    __syncthreads();
    int nid = blockIdx.x * blockDim.x + t;
    if (nid >= N_NODES) return;
    const float* xr = x + (size_t)nid * NF;
    float b0 = 0.0f, b1 = 0.0f, b2 = 0.0f;
    #pragma unroll
    for (int k = 0; k < NF; k++) {
        float xv = xr[k];
        b0 = fmaf(xv, sV[k], b0);
        b1 = fmaf(xv, sV[NF + k], b1);
        b2 = fmaf(xv, sV[2 * NF + k], b2);
    }
    g_b[nid * 3 + 0] = b0;
    g_b[nid * 3 + 1] = b1;
    g_b[nid * 3 + 2] = b2;
}

// ---------------- kernel 3: edge scatter (thread per edge, 9+1 atomics) ----------------
__global__ void k_scatter(const float* __restrict__ pos,
                          const float* __restrict__ eattr,
                          const int*   __restrict__ esrc,
                          const int*   __restrict__ edst) {
    int e = blockIdx.x * blockDim.x + threadIdx.x;
    if (e >= N_EDGES) return;
    int src = esrc[e];
    int dst = edst[e];
    float vx = pos[src * 3 + 0] - pos[dst * 3 + 0];
    float vy = pos[src * 3 + 1] - pos[dst * 3 + 1];
    float vz = pos[src * 3 + 2] - pos[dst * 3 + 2];
    float w  = eattr[(size_t)e * 10];
    g_w[e] = w;                       // compact for pass 2
    float ea[9];
    compute_ea(vx, vy, vz, w, ea);
    float b0 = g_b[src * 3 + 0];
    float b1 = g_b[src * 3 + 1];
    float b2 = g_b[src * 3 + 2];
    float* hp = g_h + (size_t)dst * 9;
    atomicAdd(hp + 0, b0 * ea[0]);
    #pragma unroll
    for (int m = 1; m < 4; m++) atomicAdd(hp + m, b1 * ea[m]);
    #pragma unroll
    for (int m = 4; m < 9; m++) atomicAdd(hp + m, b2 * ea[m]);
    atomicAdd(&g_deg[dst], 1.0f);
}

// ---------------- kernel 4: scale h by inv-sqrt-degree ----------------
__global__ void k_mid() {
    int i = blockIdx.x * blockDim.x + threadIdx.x;
    if (i >= N_NODES) return;
    float d = g_deg[i];
    float isd = (d > 0.0f) ? rsqrtf(fmaxf(d, 1.0f)) : 0.0f;
    g_isd[i] = isd;
    float* hp = g_h + (size_t)i * 9;
    #pragma unroll
    for (int m = 0; m < 9; m++) hp[m] *= isd;
}

// ---------------- kernel 5: edge gather + contraction (thread per edge, 1 atomic) ----------------
__global__ void k_gather(const float* __restrict__ pos,
                         const int* __restrict__ esrc,
                         const int* __restrict__ edst) {
    int e = blockIdx.x * blockDim.x + threadIdx.x;
    if (e >= N_EDGES) return;
    int src = esrc[e];
    int dst = edst[e];
    float vx = pos[src * 3 + 0] - pos[dst * 3 + 0];
    float vy = pos[src * 3 + 1] - pos[dst * 3 + 1];
    float vz = pos[src * 3 + 2] - pos[dst * 3 + 2];
    float w  = g_w[e];
    float ea[9];
    compute_ea(vx, vy, vz, w, ea);

    const float* hp = g_h + (size_t)src * 9;
    const float inv_s3 = 0.5773502691896258f;
    const float inv_s5 = 0.4472135954999579f;

    float t0 = hp[0] * ea[0];
    float t1 = hp[1] * ea[1] + hp[2] * ea[2] + hp[3] * ea[3];
    float t2 = hp[4] * ea[4] + hp[5] * ea[5] + hp[6] * ea[6]
             + hp[7] * ea[7] + hp[8] * ea[8];
    float out_e = (t0 + t1 * inv_s3 + t2 * inv_s5) * 0.09805806756909202f; // 1/sqrt(104)
    atomicAdd(&g_nodesum[dst], out_e);
}

// ---------------- kernel 6: node -> molecule ----------------
__global__ void k_node_to_mol(const int* __restrict__ batch) {
    int i = blockIdx.x * blockDim.x + threadIdx.x;
    if (i >= N_NODES) return;
    float v = g_nodesum[i] * g_isd[i];
    int m = batch[i];
    atomicAdd(&g_acc[m], v);
    atomicAdd(&g_atoms[m], 1.0f);
}

// ---------------- kernel 7: finalize ----------------
__global__ void k_finalize(float* __restrict__ out) {
    int m = blockIdx.x * blockDim.x + threadIdx.x;
    if (m < N_MOL) {
        float a = g_atoms[m];
        out[m] = g_acc[m] * ((a > 0.0f) ? rsqrtf(fmaxf(a, 1.0f)) : 0.0f);
    }
}

// ---------------- launch ----------------
extern "C" void kernel_launch(void* const* d_in, const int* in_sizes, int n_in,
                              void* d_out, int out_size) {
    (void)in_sizes; (void)n_in; (void)out_size;
    const float* pos   = (const float*)d_in[0];
    const float* x     = (const float*)d_in[1];
    const float* eattr = (const float*)d_in[2];
    const float* W1_0  = (const float*)d_in[3];
    const float* W1_1  = (const float*)d_in[4];
    const float* W1_2  = (const float*)d_in[5];
    const float* W2_0  = (const float*)d_in[6];
    const float* W2_1  = (const float*)d_in[7];
    const float* W2_2  = (const float*)d_in[8];
    const int* esrc    = (const int*)d_in[9];
    const int* edst    = (const int*)d_in[10];
    const int* batch   = (const int*)d_in[11];
    float* out = (float*)d_out;

    k_zero<<<(N_NODES * 9 + 255) / 256, 256>>>();
    k_V<<<1, 96>>>(W1_0, W1_1, W1_2, W2_0, W2_1, W2_2);
    k_b<<<(N_NODES + 127) / 128, 128>>>(x);

    int eblocks = (N_EDGES + 255) / 256;
    k_scatter<<<eblocks, 256>>>(pos, eattr, esrc, edst);
    k_mid<<<(N_NODES + 255) / 256, 256>>>();
    k_gather<<<eblocks, 256>>>(pos, esrc, edst);

    k_node_to_mol<<<(N_NODES + 255) / 256, 256>>>(batch);
    k_finalize<<<(N_MOL + 255) / 256, 256>>>(out);
}

// round 4
// speedup vs baseline: 8.5217x; 1.7224x over previous
#include <cuda_runtime.h>

#define N_NODES 50000
#define N_EDGES 600000
#define N_MOL   512
#define NF      30

// ---------------- scratch (device globals; no allocation) ----------------
// h layout per node (3 x float4 = 12 floats): [m0..m3][m4..m7][m8, deg, 0, 0]
__device__ float4 g_h4[(size_t)N_NODES * 3];
// packed node data (2 x float4): [px,py,pz,b0][b1,b2,0,0]
__device__ float4 g_nd[(size_t)N_NODES * 2];
__device__ float  g_w[N_EDGES];          // edge_attr[:,0] compacted
__device__ float  g_isd[N_NODES];
__device__ float  g_nodesum[N_NODES];
__device__ float  g_acc[N_MOL];
__device__ float  g_atoms[N_MOL];

__device__ __forceinline__ void atomic_add_f4(float4* p, float4 v) {
#if defined(__CUDA_ARCH__) && (__CUDA_ARCH__ >= 900)
    atomicAdd(p, v);
#else
    float* s = (float*)p;
    atomicAdd(s + 0, v.x);
    atomicAdd(s + 1, v.y);
    atomicAdd(s + 2, v.z);
    atomicAdd(s + 3, v.w);
#endif
}

__device__ __forceinline__ void compute_ea(float x, float y, float z, float w, float* ea) {
    const float s3  = 1.7320508075688772f;
    const float s5  = 2.2360679774997896f;
    const float s15 = 3.8729833462074170f;
    float r2 = x * x + y * y + z * z;
    ea[0] = w;
    ea[1] = w * s3 * x;
    ea[2] = w * s3 * y;
    ea[3] = w * s3 * z;
    ea[4] = w * s15 * x * y;
    ea[5] = w * s15 * y * z;
    ea[6] = w * 0.5f * s5 * (3.0f * z * z - r2);
    ea[7] = w * s15 * x * z;
    ea[8] = w * 0.5f * s15 * (x * x - y * y);
}

// ---------------- kernel 0: zero scratch + extract edge_attr col 0 ----------------
__global__ void k_init(const float* __restrict__ eattr) {
    int i = blockIdx.x * blockDim.x + threadIdx.x;
    if (i < N_EDGES) g_w[i] = __ldcs(eattr + (size_t)i * 10);
    if (i < N_NODES * 3) g_h4[i] = make_float4(0.f, 0.f, 0.f, 0.f);
    if (i < N_NODES) g_nodesum[i] = 0.0f;
    if (i < N_MOL)  { g_acc[i] = 0.0f; g_atoms[i] = 0.0f; }
}

// ---------------- kernel 1: V = (W1_l @ W2_l)/sqrt(30) per-block, then b = x@V + pack pos ----------------
__global__ void k_b(const float* __restrict__ x,
                    const float* __restrict__ pos,
                    const float* __restrict__ W1_0,
                    const float* __restrict__ W1_1,
                    const float* __restrict__ W1_2,
                    const float* __restrict__ W2_0,
                    const float* __restrict__ W2_1,
                    const float* __restrict__ W2_2) {
    __shared__ float sV[3 * NF];
    int t = threadIdx.x;
    const float inv_s30 = 0.18257418583505536f;
    if (t < NF) {
        float acc = 0.0f;
        #pragma unroll
        for (int u = 0; u < 64; u++) acc = fmaf(W1_0[t * 64 + u], W2_0[u], acc);
        sV[t] = acc * inv_s30;
    } else if (t < 2 * NF) {
        int k = t - NF;
        float acc = 0.0f;
        #pragma unroll
        for (int u = 0; u < 24; u++) acc = fmaf(W1_1[k * 24 + u], W2_1[u], acc);
        sV[t] = acc * inv_s30;
    } else if (t < 3 * NF) {
        int k = t - 2 * NF;
        float acc = 0.0f;
        #pragma unroll
        for (int u = 0; u < 16; u++) acc = fmaf(W1_2[k * 16 + u], W2_2[u], acc);
        sV[t] = acc * inv_s30;
    }
    __syncthreads();
    int nid = blockIdx.x * blockDim.x + t;
    if (nid >= N_NODES) return;
    const float* xr = x + (size_t)nid * NF;
    float b0 = 0.0f, b1 = 0.0f, b2 = 0.0f;
    #pragma unroll
    for (int k = 0; k < NF; k++) {
        float xv = xr[k];
        b0 = fmaf(xv, sV[k], b0);
        b1 = fmaf(xv, sV[NF + k], b1);
        b2 = fmaf(xv, sV[2 * NF + k], b2);
    }
    float px = pos[nid * 3 + 0];
    float py = pos[nid * 3 + 1];
    float pz = pos[nid * 3 + 2];
    g_nd[(size_t)nid * 2 + 0] = make_float4(px, py, pz, b0);
    g_nd[(size_t)nid * 2 + 1] = make_float4(b1, b2, 0.f, 0.f);
}

// ---------------- kernel 2: edge scatter (3 float4 atomics per edge) ----------------
__global__ void k_scatter(const int* __restrict__ esrc,
                          const int* __restrict__ edst) {
    int e = blockIdx.x * blockDim.x + threadIdx.x;
    if (e >= N_EDGES) return;
    int src = esrc[e];
    int dst = edst[e];
    float4 s0 = g_nd[(size_t)src * 2 + 0];
    float4 s1 = g_nd[(size_t)src * 2 + 1];
    float4 d0 = g_nd[(size_t)dst * 2 + 0];
    float vx = s0.x - d0.x, vy = s0.y - d0.y, vz = s0.z - d0.z;
    float w = g_w[e];
    float ea[9];
    compute_ea(vx, vy, vz, w, ea);
    float b0 = s0.w, b1 = s1.x, b2 = s1.y;
    float4* hp = g_h4 + (size_t)dst * 3;
    atomic_add_f4(hp + 0, make_float4(b0 * ea[0], b1 * ea[1], b1 * ea[2], b1 * ea[3]));
    atomic_add_f4(hp + 1, make_float4(b2 * ea[4], b2 * ea[5], b2 * ea[6], b2 * ea[7]));
    atomic_add_f4(hp + 2, make_float4(b2 * ea[8], 1.0f, 0.f, 0.f));
}

// ---------------- kernel 3: isd from deg; scale h by isd ----------------
__global__ void k_mid() {
    int i = blockIdx.x * blockDim.x + threadIdx.x;
    if (i >= N_NODES) return;
    float4 h0 = g_h4[(size_t)i * 3 + 0];
    float4 h1 = g_h4[(size_t)i * 3 + 1];
    float4 h2 = g_h4[(size_t)i * 3 + 2];
    float d = h2.y;
    float isd = (d > 0.0f) ? rsqrtf(fmaxf(d, 1.0f)) : 0.0f;
    g_isd[i] = isd;
    h0.x *= isd; h0.y *= isd; h0.z *= isd; h0.w *= isd;
    h1.x *= isd; h1.y *= isd; h1.z *= isd; h1.w *= isd;
    h2.x *= isd;
    g_h4[(size_t)i * 3 + 0] = h0;
    g_h4[(size_t)i * 3 + 1] = h1;
    g_h4[(size_t)i * 3 + 2] = h2;
}

// ---------------- kernel 4: edge gather + contraction (1 scalar atomic) ----------------
__global__ void k_gather(const int* __restrict__ esrc,
                         const int* __restrict__ edst) {
    int e = blockIdx.x * blockDim.x + threadIdx.x;
    if (e >= N_EDGES) return;
    int src = esrc[e];
    int dst = edst[e];
    float4 s0 = g_nd[(size_t)src * 2 + 0];
    float4 d0 = g_nd[(size_t)dst * 2 + 0];
    float vx = s0.x - d0.x, vy = s0.y - d0.y, vz = s0.z - d0.z;
    float w = g_w[e];
    float ea[9];
    compute_ea(vx, vy, vz, w, ea);

    float4 h0 = g_h4[(size_t)src * 3 + 0];
    float4 h1 = g_h4[(size_t)src * 3 + 1];
    float4 h2 = g_h4[(size_t)src * 3 + 2];

    const float inv_s3 = 0.5773502691896258f;
    const float inv_s5 = 0.4472135954999579f;

    float t0 = h0.x * ea[0];
    float t1 = h0.y * ea[1] + h0.z * ea[2] + h0.w * ea[3];
    float t2 = h1.x * ea[4] + h1.y * ea[5] + h1.z * ea[6]
             + h1.w * ea[7] + h2.x * ea[8];
    float out_e = (t0 + t1 * inv_s3 + t2 * inv_s5) * 0.09805806756909202f; // 1/sqrt(104)
    atomicAdd(&g_nodesum[dst], out_e);
}

// ---------------- kernel 5: node -> molecule (run-accumulated; batch is sorted) ----------------
__global__ void k_node_to_mol(const int* __restrict__ batch) {
    int t = blockIdx.x * blockDim.x + threadIdx.x;
    int base = t * 8;
    if (base >= N_NODES) return;
    int cur = -1;
    float acc = 0.0f, cnt = 0.0f;
    #pragma unroll
    for (int j = 0; j < 8; j++) {
        int i = base + j;
        if (i >= N_NODES) break;
        int m = batch[i];
        float v = g_nodesum[i] * g_isd[i];
        if (m != cur) {
            if (cur >= 0) { atomicAdd(&g_acc[cur], acc); atomicAdd(&g_atoms[cur], cnt); }
            cur = m; acc = 0.0f; cnt = 0.0f;
        }
        acc += v; cnt += 1.0f;
    }
    if (cur >= 0) { atomicAdd(&g_acc[cur], acc); atomicAdd(&g_atoms[cur], cnt); }
}

// ---------------- kernel 6: finalize ----------------
__global__ void k_finalize(float* __restrict__ out) {
    int m = blockIdx.x * blockDim.x + threadIdx.x;
    if (m < N_MOL) {
        float a = g_atoms[m];
        out[m] = g_acc[m] * ((a > 0.0f) ? rsqrtf(fmaxf(a, 1.0f)) : 0.0f);
    }
}

// ---------------- launch ----------------
extern "C" void kernel_launch(void* const* d_in, const int* in_sizes, int n_in,
                              void* d_out, int out_size) {
    (void)in_sizes; (void)n_in; (void)out_size;
    const float* pos   = (const float*)d_in[0];
    const float* x     = (const float*)d_in[1];
    const float* eattr = (const float*)d_in[2];
    const float* W1_0  = (const float*)d_in[3];
    const float* W1_1  = (const float*)d_in[4];
    const float* W1_2  = (const float*)d_in[5];
    const float* W2_0  = (const float*)d_in[6];
    const float* W2_1  = (const float*)d_in[7];
    const float* W2_2  = (const float*)d_in[8];
    const int* esrc    = (const int*)d_in[9];
    const int* edst    = (const int*)d_in[10];
    const int* batch   = (const int*)d_in[11];
    float* out = (float*)d_out;

    k_init<<<(N_EDGES + 255) / 256, 256>>>(eattr);
    k_b<<<(N_NODES + 127) / 128, 128>>>(x, pos, W1_0, W1_1, W1_2, W2_0, W2_1, W2_2);

    int eblocks = (N_EDGES + 255) / 256;
    k_scatter<<<eblocks, 256>>>(esrc, edst);
    k_mid<<<(N_NODES + 255) / 256, 256>>>();
    k_gather<<<eblocks, 256>>>(esrc, edst);

    k_node_to_mol<<<(N_NODES / 8 + 255) / 256, 256>>>(batch);
    k_finalize<<<1, N_MOL>>>(out);
}

// round 5
// speedup vs baseline: 9.3745x; 1.1001x over previous
#include <cuda_runtime.h>

#define N_NODES 50000
#define N_EDGES 600000
#define N_MOL   512
#define NF      30

// ---------------- scratch (device globals; no allocation) ----------------
// h layout per node (3 x float4 = 12 floats): [m0..m3][m4..m7][m8, deg, 0, 0]
__device__ float4 g_h4[(size_t)N_NODES * 3];
// packed node data (2 x float4): [px,py,pz,b0][b1,b2,0,0]
__device__ float4 g_nd[(size_t)N_NODES * 2];
__device__ float  g_w[N_EDGES];          // edge_attr[:,0] compacted
__device__ float  g_nodesum[N_NODES];
__device__ float  g_acc[N_MOL];
__device__ float  g_atoms[N_MOL];

#define NODE_BLOCKS ((N_NODES + 255) / 256)

__device__ __forceinline__ void atomic_add_f4(float4* p, float4 v) {
#if defined(__CUDA_ARCH__) && (__CUDA_ARCH__ >= 900)
    atomicAdd(p, v);
#else
    float* s = (float*)p;
    atomicAdd(s + 0, v.x);
    atomicAdd(s + 1, v.y);
    atomicAdd(s + 2, v.z);
    atomicAdd(s + 3, v.w);
#endif
}

__device__ __forceinline__ float inv_sqrt_deg(float d) {
    return (d > 0.0f) ? rsqrtf(fmaxf(d, 1.0f)) : 0.0f;
}

__device__ __forceinline__ void compute_ea(float x, float y, float z, float w, float* ea) {
    const float s3  = 1.7320508075688772f;
    const float s5  = 2.2360679774997896f;
    const float s15 = 3.8729833462074170f;
    float r2 = x * x + y * y + z * z;
    ea[0] = w;
    ea[1] = w * s3 * x;
    ea[2] = w * s3 * y;
    ea[3] = w * s3 * z;
    ea[4] = w * s15 * x * y;
    ea[5] = w * s15 * y * z;
    ea[6] = w * 0.5f * s5 * (3.0f * z * z - r2);
    ea[7] = w * s15 * x * z;
    ea[8] = w * 0.5f * s15 * (x * x - y * y);
}

// ---------------- kernel 0 (fused prep): zero + w-extract + b = x@V + pos pack ----------------
__global__ void k_prep(const float* __restrict__ eattr,
                       const float* __restrict__ x,
                       const float* __restrict__ pos,
                       const float* __restrict__ W1_0,
                       const float* __restrict__ W1_1,
                       const float* __restrict__ W1_2,
                       const float* __restrict__ W2_0,
                       const float* __restrict__ W2_1,
                       const float* __restrict__ W2_2) {
    __shared__ float sV[3 * NF];
    int t = threadIdx.x;
    int i = blockIdx.x * blockDim.x + t;

    // V = (W1_l @ W2_l)/sqrt(30), only in blocks that will compute b
    if (blockIdx.x < NODE_BLOCKS) {
        const float inv_s30 = 0.18257418583505536f;
        if (t < NF) {
            float acc = 0.0f;
            #pragma unroll
            for (int u = 0; u < 64; u++) acc = fmaf(W1_0[t * 64 + u], W2_0[u], acc);
            sV[t] = acc * inv_s30;
        } else if (t < 2 * NF) {
            int k = t - NF;
            float acc = 0.0f;
            #pragma unroll
            for (int u = 0; u < 24; u++) acc = fmaf(W1_1[k * 24 + u], W2_1[u], acc);
            sV[t] = acc * inv_s30;
        } else if (t < 3 * NF) {
            int k = t - 2 * NF;
            float acc = 0.0f;
            #pragma unroll
            for (int u = 0; u < 16; u++) acc = fmaf(W1_2[k * 16 + u], W2_2[u], acc);
            sV[t] = acc * inv_s30;
        }
        __syncthreads();
    }

    // compact edge weight (streams the 24 MB edge_attr once)
    if (i < N_EDGES) g_w[i] = __ldcs(eattr + (size_t)i * 10);

    // zero scratch
    if (i < N_NODES * 3) g_h4[i] = make_float4(0.f, 0.f, 0.f, 0.f);
    if (i < N_NODES) g_nodesum[i] = 0.0f;
    if (i < N_MOL)  { g_acc[i] = 0.0f; g_atoms[i] = 0.0f; }

    // b = x @ V, packed with position
    if (i < N_NODES) {
        const float* xr = x + (size_t)i * NF;
        float b0 = 0.0f, b1 = 0.0f, b2 = 0.0f;
        #pragma unroll
        for (int k = 0; k < NF; k++) {
            float xv = xr[k];
            b0 = fmaf(xv, sV[k], b0);
            b1 = fmaf(xv, sV[NF + k], b1);
            b2 = fmaf(xv, sV[2 * NF + k], b2);
        }
        float px = pos[i * 3 + 0];
        float py = pos[i * 3 + 1];
        float pz = pos[i * 3 + 2];
        g_nd[(size_t)i * 2 + 0] = make_float4(px, py, pz, b0);
        g_nd[(size_t)i * 2 + 1] = make_float4(b1, b2, 0.f, 0.f);
    }
}

// ---------------- kernel 1: edge scatter (3 float4 atomics per edge) ----------------
__global__ void k_scatter(const int* __restrict__ esrc,
                          const int* __restrict__ edst) {
    int e = blockIdx.x * blockDim.x + threadIdx.x;
    if (e >= N_EDGES) return;
    int src = esrc[e];
    int dst = edst[e];
    float4 s0 = g_nd[(size_t)src * 2 + 0];
    float4 s1 = g_nd[(size_t)src * 2 + 1];
    float4 d0 = g_nd[(size_t)dst * 2 + 0];
    float vx = s0.x - d0.x, vy = s0.y - d0.y, vz = s0.z - d0.z;
    float w = g_w[e];
    float ea[9];
    compute_ea(vx, vy, vz, w, ea);
    float b0 = s0.w, b1 = s1.x, b2 = s1.y;
    float4* hp = g_h4 + (size_t)dst * 3;
    atomic_add_f4(hp + 0, make_float4(b0 * ea[0], b1 * ea[1], b1 * ea[2], b1 * ea[3]));
    atomic_add_f4(hp + 1, make_float4(b2 * ea[4], b2 * ea[5], b2 * ea[6], b2 * ea[7]));
    atomic_add_f4(hp + 2, make_float4(b2 * ea[8], 1.0f, 0.f, 0.f));
}

// ---------------- kernel 2: edge gather + contraction (isd inline; 1 scalar atomic) ----------------
__global__ void k_gather(const int* __restrict__ esrc,
                         const int* __restrict__ edst) {
    int e = blockIdx.x * blockDim.x + threadIdx.x;
    if (e >= N_EDGES) return;
    int src = esrc[e];
    int dst = edst[e];
    float4 s0 = g_nd[(size_t)src * 2 + 0];
    float4 d0 = g_nd[(size_t)dst * 2 + 0];
    float vx = s0.x - d0.x, vy = s0.y - d0.y, vz = s0.z - d0.z;
    float w = g_w[e];
    float ea[9];
    compute_ea(vx, vy, vz, w, ea);

    float4 h0 = g_h4[(size_t)src * 3 + 0];
    float4 h1 = g_h4[(size_t)src * 3 + 1];
    float4 h2 = g_h4[(size_t)src * 3 + 2];
    float isd_src = inv_sqrt_deg(h2.y);

    const float inv_s3 = 0.5773502691896258f;
    const float inv_s5 = 0.4472135954999579f;

    float t0 = h0.x * ea[0];
    float t1 = h0.y * ea[1] + h0.z * ea[2] + h0.w * ea[3];
    float t2 = h1.x * ea[4] + h1.y * ea[5] + h1.z * ea[6]
             + h1.w * ea[7] + h2.x * ea[8];
    float out_e = (t0 + t1 * inv_s3 + t2 * inv_s5) * isd_src * 0.09805806756909202f;
    atomicAdd(&g_nodesum[dst], out_e);
}

// ---------------- kernel 3: node -> molecule (run-accumulated; batch is sorted) ----------------
__global__ void k_node_to_mol(const int* __restrict__ batch) {
    int t = blockIdx.x * blockDim.x + threadIdx.x;
    int base = t * 8;
    if (base >= N_NODES) return;
    int cur = -1;
    float acc = 0.0f, cnt = 0.0f;
    #pragma unroll
    for (int j = 0; j < 8; j++) {
        int i = base + j;
        if (i >= N_NODES) break;
        int m = batch[i];
        float isd = inv_sqrt_deg(g_h4[(size_t)i * 3 + 2].y);
        float v = g_nodesum[i] * isd;
        if (m != cur) {
            if (cur >= 0) { atomicAdd(&g_acc[cur], acc); atomicAdd(&g_atoms[cur], cnt); }
            cur = m; acc = 0.0f; cnt = 0.0f;
        }
        acc += v; cnt += 1.0f;
    }
    if (cur >= 0) { atomicAdd(&g_acc[cur], acc); atomicAdd(&g_atoms[cur], cnt); }
}

// ---------------- kernel 4: finalize ----------------
__global__ void k_finalize(float* __restrict__ out) {
    int m = blockIdx.x * blockDim.x + threadIdx.x;
    if (m < N_MOL) {
        float a = g_atoms[m];
        out[m] = g_acc[m] * ((a > 0.0f) ? rsqrtf(fmaxf(a, 1.0f)) : 0.0f);
    }
}

// ---------------- launch ----------------
extern "C" void kernel_launch(void* const* d_in, const int* in_sizes, int n_in,
                              void* d_out, int out_size) {
    (void)in_sizes; (void)n_in; (void)out_size;
    const float* pos   = (const float*)d_in[0];
    const float* x     = (const float*)d_in[1];
    const float* eattr = (const float*)d_in[2];
    const float* W1_0  = (const float*)d_in[3];
    const float* W1_1  = (const float*)d_in[4];
    const float* W1_2  = (const float*)d_in[5];
    const float* W2_0  = (const float*)d_in[6];
    const float* W2_1  = (const float*)d_in[7];
    const float* W2_2  = (const float*)d_in[8];
    const int* esrc    = (const int*)d_in[9];
    const int* edst    = (const int*)d_in[10];
    const int* batch   = (const int*)d_in[11];
    float* out = (float*)d_out;

    int eblocks = (N_EDGES + 255) / 256;
    k_prep<<<eblocks, 256>>>(eattr, x, pos, W1_0, W1_1, W1_2, W2_0, W2_1, W2_2);
    k_scatter<<<eblocks, 256>>>(esrc, edst);
    k_gather<<<eblocks, 256>>>(esrc, edst);
    k_node_to_mol<<<(N_NODES / 8 + 255) / 256, 256>>>(batch);
    k_finalize<<<1, N_MOL>>>(out);
}